// round 14
// baseline (speedup 1.0000x reference)
#include <cuda_runtime.h>
#include <cuda_fp16.h>
#include <math.h>
#include <stdint.h>

#define NB   16
#define NC   256
#define NC8  32
#define HW   96
#define PIX  (HW*HW)     /* 9216 */
#define KK   11
#define KTOT (NC*KK)     /* 2816 */

typedef unsigned long long ull;

// ---------------- scratch (static device globals; no allocation) -------------
__device__ float g_xT [NB*NC*PIX];    // x transposed [b,c,w,h]; reused as ohT later
__device__ float g_qw [NB*NC8*PIX];
__device__ float g_kw [NB*NC8*PIX];
__device__ float g_qhT[NB*NC8*PIX];
__device__ float g_khT[NB*NC8*PIX];
__device__ float g_vw [NB*NC*PIX];
__device__ float g_vhT[NB*NC*PIX];
__device__ float g_eh [NB*HW*PIX];    // [b,w,h,H]
__device__ float g_ew [NB*HW*PIX];    // [b,h,w,W]
__device__ float g_tmp[NB*NC*PIX];    // out_w in normal layout
// pre-packed operands (smem bit-layouts, enables cp.async staging)
__device__ __align__(16) uint32_t g_x2  [NB*128*PIX];   // half2(x[2p], x[2p+1])
__device__ __align__(16) uint32_t g_x2T [NB*128*PIX];
__device__ __align__(16) uint32_t g_wv2 [2*NC*1408];    // [conv][o][kc*88 + c2*11 + t], 16 chunks
__device__ __align__(16) ull      g_wqk2[4*16*2816];    // [conv][opair][kc*88 + c*11 + t], 32 chunks

// ---------------- helpers ----------------------------------------------------
__device__ __forceinline__ uint32_t pack_h2(float a, float b) {
    __half2 h = __floats2half2_rn(a, b);
    return *reinterpret_cast<uint32_t*>(&h);
}

__device__ __forceinline__ void mma_f16(float c[4],
    uint32_t a0, uint32_t a1, uint32_t a2, uint32_t a3,
    uint32_t b0, uint32_t b1)
{
    asm volatile(
        "mma.sync.aligned.m16n8k16.row.col.f32.f16.f16.f32 "
        "{%0,%1,%2,%3}, {%4,%5,%6,%7}, {%8,%9}, {%0,%1,%2,%3};"
        : "+f"(c[0]), "+f"(c[1]), "+f"(c[2]), "+f"(c[3])
        : "r"(a0), "r"(a1), "r"(a2), "r"(a3), "r"(b0), "r"(b1));
}

// packed fp32x2: two exact IEEE fp32 FMAs per instruction (Blackwell FFMA2)
__device__ __forceinline__ ull ffma2(ull a, ull b, ull c) {
    ull d;
    asm("fma.rn.f32x2 %0, %1, %2, %3;" : "=l"(d) : "l"(a), "l"(b), "l"(c));
    return d;
}
__device__ __forceinline__ ull pack2(float lo, float hi) {
    ull r;
    asm("mov.b64 %0, {%1, %2};" : "=l"(r) : "f"(lo), "f"(hi));
    return r;
}
__device__ __forceinline__ void unpack2(ull v, float& lo, float& hi) {
    asm("mov.b64 {%0, %1}, %2;" : "=f"(lo), "=f"(hi) : "l"(v));
}

__device__ __forceinline__ void cp_async4(uint32_t s, const void* g) {
    asm volatile("cp.async.ca.shared.global [%0], [%1], 4;" :: "r"(s), "l"(g));
}
__device__ __forceinline__ void cp_async16(uint32_t s, const void* g) {
    asm volatile("cp.async.cg.shared.global [%0], [%1], 16;" :: "r"(s), "l"(g));
}
#define CP_COMMIT() asm volatile("cp.async.commit_group;" ::: "memory")
#define CP_WAIT0()  asm volatile("cp.async.wait_group 0;" ::: "memory")

// ---------------- tiled transpose: out[b,c,w,h] = in[b,c,h,w] ----------------
__global__ void transpose_kernel(const float* __restrict__ in, float* __restrict__ out)
{
    __shared__ float ts[32][33];
    const int tile = blockIdx.x;            // 0..8
    const int plane = blockIdx.y;           // b*C + c
    const int h0 = (tile % 3) * 32, w0 = (tile / 3) * 32;
    const float* ib = in + (size_t)plane * PIX;
    float* ob = out + (size_t)plane * PIX;
    const int col = threadIdx.x & 31, row = threadIdx.x >> 5;
    #pragma unroll
    for (int r = 0; r < 4; r++) {
        int h = row + r*8;
        ts[h][col] = ib[(h0 + h)*HW + w0 + col];
    }
    __syncthreads();
    #pragma unroll
    for (int r = 0; r < 4; r++) {
        int w = row + r*8;
        ob[(w0 + w)*HW + h0 + col] = ts[col][w];
    }
}

// ---------------- prep: pack x / xT into half2 channel pairs -----------------
__global__ void pack_x2_kernel(const float* __restrict__ x, const float* __restrict__ xT,
                               uint32_t* __restrict__ x2, uint32_t* __restrict__ x2T)
{
    size_t idx = (size_t)blockIdx.x * 256 + threadIdx.x;      // < NB*128*PIX
    const float* src = blockIdx.y ? xT : x;
    uint32_t* dst    = blockIdx.y ? x2T : x2;
    size_t bp = idx / PIX, pix = idx % PIX;
    size_t b = bp >> 7, pr = bp & 127;
    const float* s = src + (b*NC + 2*pr) * (size_t)PIX + pix;
    dst[idx] = pack_h2(s[0], s[PIX]);
}

// ---------------- prep: pack v weights (half2 chunk layout, 16 chunks) -------
__global__ void pack_wv2_kernel(const float* __restrict__ wv_w, const float* __restrict__ wv_h,
                                uint32_t* __restrict__ dst)
{
    int i = blockIdx.x * 256 + threadIdx.x;                   // < 2*NC*1408
    int conv = i / (NC*1408);
    int r = i % (NC*1408);
    int o = r / 1408, k = r % 1408;
    int kc = k / 88, rr = k % 88, c2 = rr / 11, t = rr % 11;
    const float* w = conv ? wv_h : wv_w;
    int c = kc*16 + 2*c2;
    dst[i] = pack_h2(w[(size_t)o*KTOT + c*KK + t], w[(size_t)o*KTOT + (c+1)*KK + t]);
}

// ---------------- prep: pack qk weights (fp32x2 (o,o+16), 32 chunks) ---------
__global__ void pack_wqk2_kernel(const float* __restrict__ w0, const float* __restrict__ w1,
                                 const float* __restrict__ w2, const float* __restrict__ w3,
                                 ull* __restrict__ dst)
{
    int i = blockIdx.x * 256 + threadIdx.x;                   // < 4*16*2816
    int conv = i / (16*2816);
    int r = i % (16*2816);
    int o = r / 2816, k = r % 2816;
    int kc = k / 88, rr = k % 88, c = rr / 11, t = rr % 11;
    const float* w = (conv == 0) ? w0 : (conv == 1) ? w1 : (conv == 2) ? w2 : w3;
    int ch = kc*8 + c;
    dst[i] = pack2(w[(size_t)o*KTOT + ch*KK + t], w[(size_t)(o+16)*KTOT + ch*KK + t]);
}

// ---------------- fp32x2 packed 1-D conv (all 4 q/k convs, cp.async piped) ---
// grid = (96, 4, 16); blockIdx.y selects conv. 32 K-chunks of 8 channels.
__global__ void __launch_bounds__(256) conv1d_qk_kernel(
    const float* __restrict__ x, const float* __restrict__ xT,
    const ull* __restrict__ wpk,
    const float* __restrict__ bq_w, float* __restrict__ qw_o,
    const float* __restrict__ bk_w, float* __restrict__ kw_o,
    const float* __restrict__ bq_h, float* __restrict__ qh_o,
    const float* __restrict__ bk_h, float* __restrict__ kh_o)
{
    constexpr int RQ = 6;
    __shared__ float in_s[2][8][112];        // pos 5..100 valid, halo zero
    __shared__ ull   w2_s[2][16][88];

    const int conv = blockIdx.y;
    const float* in; const float* bias; float* out;
    switch (conv) {
        case 0:  in = x;  bias = bq_w; out = qw_o; break;
        case 1:  in = x;  bias = bk_w; out = kw_o; break;
        case 2:  in = xT; bias = bq_h; out = qh_o; break;
        default: in = xT; bias = bk_h; out = kh_o; break;
    }

    const int tid = threadIdx.x;
    const int tq = tid % 16, to = tid / 16;
    const int p = blockIdx.x, b = blockIdx.z;
    const float* inb = in + (size_t)b * NC * PIX + p * HW;
    const ull* wb = wpk + (size_t)conv * 16 * 2816;

    const uint32_t su_in = (uint32_t)__cvta_generic_to_shared(&in_s[0][0][0]);
    const uint32_t su_w  = (uint32_t)__cvta_generic_to_shared(&w2_s[0][0][0]);

    // zero in_s (covers halos); must complete before first cp.async lands
    for (int i = tid; i < 2*8*112; i += 256)
        (&in_s[0][0][0])[i] = 0.f;
    __syncthreads();

    auto issue_chunk = [&](int kc, int buf) {
        // inputs: 8 rows x 96 words, 4B ops into pos+5
        #pragma unroll
        for (int it = 0; it < 3; it++) {
            int i = tid + it*256;                          // < 768
            int c = i / 96, pos = i % 96;
            uint32_t dst = su_in + (((buf*8 + c)*112) + 5 + pos) * 4;
            cp_async4(dst, inb + (size_t)(kc*8 + c) * PIX + pos);
        }
        // weights: 16 rows x 88 ull = 704 x 16B ops
        #pragma unroll
        for (int it = 0; it < 3; it++) {
            int i = tid + it*256;
            if (i < 704) {
                int o = i / 44, j = i % 44;
                uint32_t dst = su_w + (((buf*16 + o)*88) + j*2) * 8;
                cp_async16(dst, wb + (size_t)o*2816 + kc*88 + j*2);
            }
        }
        CP_COMMIT();
    };

    ull acc[RQ];
    #pragma unroll
    for (int j = 0; j < RQ; j++) acc[j] = 0ull;

    issue_chunk(0, 0);
    int buf = 0;
    for (int kc = 0; kc < 32; kc++) {
        CP_WAIT0();
        __syncthreads();
        if (kc + 1 < 32) issue_chunk(kc + 1, buf ^ 1);
        #pragma unroll 2
        for (int c = 0; c < 8; c++) {
            float xv[16];
            #pragma unroll
            for (int j = 0; j < 16; j++) xv[j] = in_s[buf][c][tq*RQ + j];
            ull xp[16];
            #pragma unroll
            for (int j = 0; j < 16; j++) xp[j] = pack2(xv[j], xv[j]);
            #pragma unroll
            for (int t = 0; t < KK; t++) {
                ull wv = w2_s[buf][to][c*KK + t];
                #pragma unroll
                for (int j = 0; j < RQ; j++)
                    acc[j] = ffma2(wv, xp[j + t], acc[j]);
            }
        }
        buf ^= 1;
    }
    const int oA = to, oB = to + 16;
    const float bA = bias[oA], bB = bias[oB];
    float* obA = out + (size_t)(b * NC8 + oA) * PIX + p * HW + tq*RQ;
    float* obB = out + (size_t)(b * NC8 + oB) * PIX + p * HW + tq*RQ;
    #pragma unroll
    for (int j = 0; j < RQ; j++) {
        float lo, hi;
        unpack2(acc[j], lo, hi);
        obA[j] = lo + bA;
        obB[j] = hi + bB;
    }
}

// ---------------- fp16 MMA 1-D conv (both v convs, cp.async piped) -----------
// Block: 64 oc x 4 lines; 8 warps = wm(0..1: 32-oc half, two m16 tiles) x
// wl(0..3: line). B fragments shared by both tiles -> 1.33 LDS/mma.
// grid = (24, 4, 32); blockIdx.z: low 4 bits = batch, bit 4 = conv.
// 16 K-chunks of 16 channels (8 half2 pairs).
#define V_SMEM ((2*4*8*120 + 2*64*92) * 4)   /* 77824 B */
__global__ void __launch_bounds__(256) conv1d_v_kernel(
    const uint32_t* __restrict__ x2, const uint32_t* __restrict__ x2T,
    const uint32_t* __restrict__ wpk,
    const float* __restrict__ bv_w, float* __restrict__ vw_o,
    const float* __restrict__ bv_h, float* __restrict__ vh_o)
{
    extern __shared__ uint32_t dsm[];
    uint32_t (*in_s)[4][8][120] = reinterpret_cast<uint32_t(*)[4][8][120]>(dsm);
    uint32_t (*w_s)[64][92]     = reinterpret_cast<uint32_t(*)[64][92]>(dsm + 2*4*8*120);

    const int zb = blockIdx.z;
    const int b = zb & 15;
    const int conv = zb >> 4;
    const uint32_t* xp = conv ? x2T : x2;
    const float* bias = conv ? bv_h : bv_w;
    float* out = conv ? vh_o : vw_o;

    const int tid = threadIdx.x;
    const int warp = tid >> 5, lane = tid & 31;
    const int wm = warp & 1;                  // 32-oc half
    const int wl = warp >> 1;                 // line 0..3
    const int krow = lane & 3;
    const int grp  = lane >> 2;
    const int p0 = blockIdx.x * 4;
    const int o0 = blockIdx.y * 64;

    const uint32_t su_in = (uint32_t)__cvta_generic_to_shared(&in_s[0][0][0][0]);
    const uint32_t su_w  = (uint32_t)__cvta_generic_to_shared(&w_s[0][0][0]);
    const uint32_t* xb = xp + ((size_t)b*128) * PIX + p0 * HW;
    const uint32_t* wb = wpk + ((size_t)conv*NC + o0) * 1408;

    // zero in_s (covers halos)
    for (int i = tid; i < 2*4*8*120; i += 256) dsm[i] = 0u;
    __syncthreads();

    auto issue_chunk = [&](int kc, int buf) {
        // inputs: 32 rows (4 lines x 8 c2) x 96 words, 4B ops into pos+5
        #pragma unroll
        for (int it = 0; it < 12; it++) {
            int i = tid + it*256;                          // < 3072
            int row = i / 96, pos = i % 96;
            int l = row >> 3, c2 = row & 7;
            uint32_t dst = su_in + ((((buf*4 + l)*8 + c2)*120) + 5 + pos) * 4;
            cp_async4(dst, xb + (size_t)(kc*8 + c2) * PIX + l*HW + pos);
        }
        // weights: 64 rows x 88 words = 1408 x 16B ops
        #pragma unroll
        for (int it = 0; it < 6; it++) {
            int i = tid + it*256;
            if (i < 1408) {
                int o = i / 22, j = i % 22;
                uint32_t dst = su_w + (((buf*64 + o)*92) + j*4) * 4;
                cp_async16(dst, wb + (size_t)o*1408 + kc*88 + j*4);
            }
        }
        CP_COMMIT();
    };

    float acc[2][12][4];
    #pragma unroll
    for (int m = 0; m < 2; m++)
        #pragma unroll
        for (int nt = 0; nt < 12; nt++)
            #pragma unroll
            for (int r = 0; r < 4; r++) acc[m][nt][r] = 0.f;

    issue_chunk(0, 0);
    int buf = 0;
    for (int kc = 0; kc < 16; kc++) {
        CP_WAIT0();
        __syncthreads();
        if (kc + 1 < 16) issue_chunk(kc + 1, buf ^ 1);
        #pragma unroll
        for (int t = 0; t < KK; t++) {
            const int r0 = wm*32 + grp;
            uint32_t a0 = w_s[buf][r0     ][ krow     *KK + t];
            uint32_t a1 = w_s[buf][r0 +  8][ krow     *KK + t];
            uint32_t a2 = w_s[buf][r0     ][(krow + 4)*KK + t];
            uint32_t a3 = w_s[buf][r0 +  8][(krow + 4)*KK + t];
            uint32_t a4 = w_s[buf][r0 + 16][ krow     *KK + t];
            uint32_t a5 = w_s[buf][r0 + 24][ krow     *KK + t];
            uint32_t a6 = w_s[buf][r0 + 16][(krow + 4)*KK + t];
            uint32_t a7 = w_s[buf][r0 + 24][(krow + 4)*KK + t];
            #pragma unroll
            for (int nt = 0; nt < 12; nt++) {
                int pos = nt*8 + grp + t;
                uint32_t b0 = in_s[buf][wl][krow    ][pos];
                uint32_t b1 = in_s[buf][wl][krow + 4][pos];
                mma_f16(acc[0][nt], a0, a1, a2, a3, b0, b1);
                mma_f16(acc[1][nt], a4, a5, a6, a7, b0, b1);
            }
        }
        buf ^= 1;
    }

    #pragma unroll
    for (int m = 0; m < 2; m++) {
        const int oLo = o0 + wm*32 + m*16 + grp;
        const int oHi = oLo + 8;
        const float bLo = bias[oLo];
        const float bHi = bias[oHi];
        float* obLo = out + (size_t)(b * NC + oLo) * PIX + (p0 + wl) * HW;
        float* obHi = out + (size_t)(b * NC + oHi) * PIX + (p0 + wl) * HW;
        #pragma unroll
        for (int nt = 0; nt < 12; nt++) {
            int q = nt*8 + 2*krow;
            obLo[q]     = acc[m][nt][0] + bLo;
            obLo[q + 1] = acc[m][nt][1] + bLo;
            obHi[q]     = acc[m][nt][2] + bHi;
            obHi[q + 1] = acc[m][nt][3] + bHi;
        }
    }
}

// ---------------- energy (both, merged): E[i,j] = sum_c Q[c,i]*K[c,j] --------
// grid = (96, 16, 2); z=0: (qhT,khT)->eh with diag mask, z=1: (qw,kw)->ew
__global__ void __launch_bounds__(256) energy_kernel(
    const float* __restrict__ qh, const float* __restrict__ kh, float* __restrict__ eh_,
    const float* __restrict__ qw, const float* __restrict__ kw, float* __restrict__ ew_)
{
    __shared__ float q_s[NC8][97], k_s[NC8][97];
    const bool diag = (blockIdx.z == 0);
    const float* q = diag ? qh : qw;
    const float* k = diag ? kh : kw;
    float* e = diag ? eh_ : ew_;
    const int l = blockIdx.x, b = blockIdx.y, tid = threadIdx.x;
    const float* qb = q + (size_t)b * NC8 * PIX + l * HW;
    const float* kb = k + (size_t)b * NC8 * PIX + l * HW;
    for (int idx = tid; idx < NC8*HW; idx += 256) {
        int c = idx / HW, i = idx % HW;
        q_s[c][i] = qb[(size_t)c * PIX + i];
        k_s[c][i] = kb[(size_t)c * PIX + i];
    }
    __syncthreads();
    const int tj = tid % 16, ti = tid / 16;
    float acc[6][6];
    #pragma unroll
    for (int i = 0; i < 6; i++)
        #pragma unroll
        for (int j = 0; j < 6; j++) acc[i][j] = 0.f;
    for (int c = 0; c < NC8; c++) {
        float qa[6], ka[6];
        #pragma unroll
        for (int ii = 0; ii < 6; ii++) qa[ii] = q_s[c][ii*16 + ti];
        #pragma unroll
        for (int jj = 0; jj < 6; jj++) ka[jj] = k_s[c][jj*16 + tj];
        #pragma unroll
        for (int ii = 0; ii < 6; ii++)
            #pragma unroll
            for (int jj = 0; jj < 6; jj++)
                acc[ii][jj] = fmaf(qa[ii], ka[jj], acc[ii][jj]);
    }
    float* eb = e + (size_t)(b * HW + l) * PIX;
    #pragma unroll
    for (int ii = 0; ii < 6; ii++)
        #pragma unroll
        for (int jj = 0; jj < 6; jj++) {
            int i = ii*16 + ti, j = jj*16 + tj;
            eb[i*HW + j] = (diag && i == j) ? -INFINITY : acc[ii][jj];
        }
}

// ---------------- softmax over concat[e_h(96), e_w(96)], in place ------------
__global__ void softmax_kernel(float* __restrict__ eh, float* __restrict__ ew)
{
    const int gw = (blockIdx.x * blockDim.x + threadIdx.x) >> 5;   // pixel id
    const int lane = threadIdx.x & 31;
    const int b = gw / PIX, rem = gw % PIX, h = rem / HW, w = rem % HW;
    float* ph = eh + ((size_t)(b*HW + w) * HW + h) * HW;
    float* pw = ew + ((size_t)(b*HW + h) * HW + w) * HW;
    float v[6];
    v[0] = ph[lane]; v[1] = ph[lane+32]; v[2] = ph[lane+64];
    v[3] = pw[lane]; v[4] = pw[lane+32]; v[5] = pw[lane+64];
    float m = v[0];
    #pragma unroll
    for (int r = 1; r < 6; r++) m = fmaxf(m, v[r]);
    #pragma unroll
    for (int s = 16; s; s >>= 1) m = fmaxf(m, __shfl_xor_sync(0xffffffffu, m, s));
    float sum = 0.f;
    #pragma unroll
    for (int r = 0; r < 6; r++) { v[r] = expf(v[r] - m); sum += v[r]; }
    #pragma unroll
    for (int s = 16; s; s >>= 1) sum += __shfl_xor_sync(0xffffffffu, sum, s);
    float inv = 1.f / sum;
    ph[lane]    = v[0]*inv; ph[lane+32] = v[1]*inv; ph[lane+64] = v[2]*inv;
    pw[lane]    = v[3]*inv; pw[lane+32] = v[4]*inv; pw[lane+64] = v[5]*inv;
}

// ---------------- apply (both, merged, FFMA2): O[c,q] = sum_k V[c,k]*A[q,k] --
// grid = (96, 16, 2); z=0: (vw, ew)->tmp, z=1: (vhT, eh)->ohT.
// A staged pre-packed (a,a) as ull; channel pairs (c, c+32) in f32x2 halves.
// Per-channel accumulation order identical to scalar version (bit-exact).
#define OUT_SMEM (96*97*8 + 64*97*4)   /* 99328 B */
__global__ void __launch_bounds__(256) out_kernel(
    const float* __restrict__ vw, const float* __restrict__ aw, float* __restrict__ ow,
    const float* __restrict__ vh, const float* __restrict__ ah, float* __restrict__ oh)
{
    extern __shared__ char sh[];
    ull   (*A2_s)[97] = reinterpret_cast<ull(*)[97]>(sh);            // [96][97] (a,a)
    float (*V_s)[97]  = reinterpret_cast<float(*)[97]>(sh + 96*97*8);// [64][97]
    const float* v; const float* a; float* o;
    if (blockIdx.z == 0) { v = vw; a = aw; o = ow; }
    else                 { v = vh; a = ah; o = oh; }
    const int l = blockIdx.x, b = blockIdx.y, tid = threadIdx.x;
    const float* ab = a + (size_t)(b*HW + l) * PIX;
    for (int idx = tid; idx < PIX; idx += 256) {
        int qq = idx / HW, kk = idx % HW;
        float av = ab[idx];
        A2_s[kk][qq] = pack2(av, av);          // transposed store
    }
    const float* vb = v + (size_t)b * NC * PIX + l * HW;
    float* ob = o + (size_t)b * NC * PIX + l * HW;
    const int tq = tid % 16, tc = tid / 16;
    for (int c0 = 0; c0 < NC; c0 += 64) {
        __syncthreads();
        for (int idx = tid; idx < 64*HW; idx += 256) {
            int cc = idx / HW, kk = idx % HW;
            V_s[cc][kk] = vb[(size_t)(c0 + cc) * PIX + kk];
        }
        __syncthreads();
        ull acc2[2][6];
        #pragma unroll
        for (int i = 0; i < 2; i++)
            #pragma unroll
            for (int j = 0; j < 6; j++) acc2[i][j] = 0ull;
        #pragma unroll 4
        for (int kk = 0; kk < HW; kk++) {
            ull va[2], aav[6];
            #pragma unroll
            for (int i = 0; i < 2; i++)
                va[i] = pack2(V_s[tc*2 + i][kk], V_s[tc*2 + i + 32][kk]);
            #pragma unroll
            for (int j = 0; j < 6; j++) aav[j] = A2_s[kk][j*16 + tq];
            #pragma unroll
            for (int i = 0; i < 2; i++)
                #pragma unroll
                for (int j = 0; j < 6; j++)
                    acc2[i][j] = ffma2(va[i], aav[j], acc2[i][j]);
        }
        #pragma unroll
        for (int i = 0; i < 2; i++) {
            const int cA = c0 + tc*2 + i, cB = cA + 32;
            #pragma unroll
            for (int j = 0; j < 6; j++) {
                float lo, hi;
                unpack2(acc2[i][j], lo, hi);
                ob[(size_t)cA * PIX + j*16 + tq] = lo;
                ob[(size_t)cB * PIX + j*16 + tq] = hi;
            }
        }
    }
}

// ---------------- final: out = gamma*(ohT^T + tmp) + x -----------------------
__global__ void fuse_kernel(const float* __restrict__ ohT, const float* __restrict__ tmp,
                            const float* __restrict__ x, const float* __restrict__ gamma,
                            float* __restrict__ out)
{
    __shared__ float ts[32][33];
    const int tile = blockIdx.x, plane = blockIdx.y;
    const int h0 = (tile % 3) * 32, w0 = (tile / 3) * 32;
    const size_t base = (size_t)plane * PIX;
    const int col = threadIdx.x & 31, row = threadIdx.x >> 5;
    #pragma unroll
    for (int r = 0; r < 4; r++) {
        int w = row + r*8;
        ts[w][col] = ohT[base + (w0 + w)*HW + h0 + col];
    }
    __syncthreads();
    const float g = *gamma;
    #pragma unroll
    for (int r = 0; r < 4; r++) {
        int h = row + r*8;
        size_t idx = base + (h0 + h)*HW + w0 + col;
        out[idx] = g * (ts[col][h] + tmp[idx]) + x[idx];
    }
}

// ---------------- launch ------------------------------------------------------
extern "C" void kernel_launch(void* const* d_in, const int* in_sizes, int n_in,
                              void* d_out, int out_size)
{
    (void)in_sizes; (void)n_in; (void)out_size;
    const float* x     = (const float*)d_in[0];
    const float* wq_h  = (const float*)d_in[1];
    const float* bq_h  = (const float*)d_in[2];
    const float* wq_w  = (const float*)d_in[3];
    const float* bq_w  = (const float*)d_in[4];
    const float* wk_h  = (const float*)d_in[5];
    const float* bk_h  = (const float*)d_in[6];
    const float* wk_w  = (const float*)d_in[7];
    const float* bk_w  = (const float*)d_in[8];
    const float* wv_h  = (const float*)d_in[9];
    const float* bv_h  = (const float*)d_in[10];
    const float* wv_w  = (const float*)d_in[11];
    const float* bv_w  = (const float*)d_in[12];
    const float* gamma = (const float*)d_in[13];
    float* out = (float*)d_out;

    float *xT, *qw, *kw, *qhT, *khT, *vw, *vhT, *eh, *ew, *tmp;
    uint32_t *x2, *x2T, *wv2; ull* wqk2;
    cudaGetSymbolAddress((void**)&xT,  g_xT);
    cudaGetSymbolAddress((void**)&qw,  g_qw);
    cudaGetSymbolAddress((void**)&kw,  g_kw);
    cudaGetSymbolAddress((void**)&qhT, g_qhT);
    cudaGetSymbolAddress((void**)&khT, g_khT);
    cudaGetSymbolAddress((void**)&vw,  g_vw);
    cudaGetSymbolAddress((void**)&vhT, g_vhT);
    cudaGetSymbolAddress((void**)&eh,  g_eh);
    cudaGetSymbolAddress((void**)&ew,  g_ew);
    cudaGetSymbolAddress((void**)&tmp, g_tmp);
    cudaGetSymbolAddress((void**)&x2,  g_x2);
    cudaGetSymbolAddress((void**)&x2T, g_x2T);
    cudaGetSymbolAddress((void**)&wv2, g_wv2);
    cudaGetSymbolAddress((void**)&wqk2, g_wqk2);
    float* ohT = xT;   // reuse: xT dead after conv phase

    cudaFuncSetAttribute((const void*)out_kernel,
                         cudaFuncAttributeMaxDynamicSharedMemorySize, OUT_SMEM);
    cudaFuncSetAttribute((const void*)conv1d_v_kernel,
                         cudaFuncAttributeMaxDynamicSharedMemorySize, V_SMEM);

    // 1) transpose x; pack operands into smem bit-layouts
    transpose_kernel<<<dim3(9, NB*NC), 256>>>(x, xT);
    pack_x2_kernel<<<dim3(NB*128*PIX/256, 2), 256>>>(x, xT, x2, x2T);
    pack_wv2_kernel<<<2*NC*1408/256, 256>>>(wv_w, wv_h, wv2);
    pack_wqk2_kernel<<<4*16*2816/256, 256>>>(wq_w, wk_w, wq_h, wk_h, wqk2);
    // 2) q/k convs (fp32x2 FFMA2, cp.async double-buffered)
    conv1d_qk_kernel<<<dim3(HW, 4, NB), 256>>>(
        x, xT, wqk2,
        bq_w, qw, bk_w, kw, bq_h, qhT, bk_h, khT);
    //    v convs (fp16 mma, 32 oc/warp, cp.async double-buffered)
    conv1d_v_kernel<<<dim3(HW/4, NC/64, 2*NB), 256, V_SMEM>>>(
        x2, x2T, wv2, bv_w, vw, bv_h, vhT);
    // 3) energies, one launch (+ diag mask on e_h)
    energy_kernel<<<dim3(HW, NB, 2), 256>>>(qhT, khT, eh, qw, kw, ew);
    // 4) joint softmax over 192, in place -> attention maps
    softmax_kernel<<<(NB*PIX)/8, 256>>>(eh, ew);
    // 5) apply attention, one launch (FFMA2 packed channel pairs)
    out_kernel<<<dim3(HW, NB, 2), 256, OUT_SMEM>>>(vw, ew, tmp, vhT, eh, ohT);
    // 6) fuse: gamma*(out_h + out_w) + x
    fuse_kernel<<<dim3(9, NB*NC), 256>>>(ohT, tmp, x, gamma, out);
}

// round 15
// speedup vs baseline: 1.0541x; 1.0541x over previous
#include <cuda_runtime.h>
#include <cuda_fp16.h>
#include <math.h>
#include <stdint.h>

#define NB   16
#define NC   256
#define NC8  32
#define HW   96
#define PIX  (HW*HW)     /* 9216 */
#define KK   11
#define KTOT (NC*KK)     /* 2816 */

typedef unsigned long long ull;

// ---------------- scratch (static device globals; no allocation) -------------
__device__ float g_xT [NB*NC*PIX];    // x transposed [b,c,w,h]; reused as ohT later
__device__ float g_qw [NB*NC8*PIX];
__device__ float g_kw [NB*NC8*PIX];
__device__ float g_qhT[NB*NC8*PIX];
__device__ float g_khT[NB*NC8*PIX];
__device__ float g_vw [NB*NC*PIX];
__device__ float g_vhT[NB*NC*PIX];
__device__ float g_eh [NB*HW*PIX];    // [b,w,h,H]
__device__ float g_ew [NB*HW*PIX];    // [b,h,w,W]
__device__ float g_tmp[NB*NC*PIX];    // out_w in normal layout
// pre-packed operands (smem bit-layouts, enables cp.async staging)
__device__ __align__(16) uint32_t g_x2  [NB*128*PIX];   // half2(x[2p], x[2p+1])
__device__ __align__(16) uint32_t g_x2T [NB*128*PIX];
__device__ __align__(16) uint32_t g_wv2 [2*NC*1408];    // [conv][o][kc*88 + c2*11 + t], 16 chunks
__device__ __align__(16) ull      g_wqk2[4*16*2816];    // [conv][opair][kc*88 + c*11 + t], 32 chunks

// ---------------- helpers ----------------------------------------------------
__device__ __forceinline__ uint32_t pack_h2(float a, float b) {
    __half2 h = __floats2half2_rn(a, b);
    return *reinterpret_cast<uint32_t*>(&h);
}

__device__ __forceinline__ void mma_f16(float c[4],
    uint32_t a0, uint32_t a1, uint32_t a2, uint32_t a3,
    uint32_t b0, uint32_t b1)
{
    asm volatile(
        "mma.sync.aligned.m16n8k16.row.col.f32.f16.f16.f32 "
        "{%0,%1,%2,%3}, {%4,%5,%6,%7}, {%8,%9}, {%0,%1,%2,%3};"
        : "+f"(c[0]), "+f"(c[1]), "+f"(c[2]), "+f"(c[3])
        : "r"(a0), "r"(a1), "r"(a2), "r"(a3), "r"(b0), "r"(b1));
}

// packed fp32x2: two exact IEEE fp32 FMAs per instruction (Blackwell FFMA2)
__device__ __forceinline__ ull ffma2(ull a, ull b, ull c) {
    ull d;
    asm("fma.rn.f32x2 %0, %1, %2, %3;" : "=l"(d) : "l"(a), "l"(b), "l"(c));
    return d;
}
__device__ __forceinline__ ull pack2(float lo, float hi) {
    ull r;
    asm("mov.b64 %0, {%1, %2};" : "=l"(r) : "f"(lo), "f"(hi));
    return r;
}
__device__ __forceinline__ void unpack2(ull v, float& lo, float& hi) {
    asm("mov.b64 {%0, %1}, %2;" : "=f"(lo), "=f"(hi) : "l"(v));
}

__device__ __forceinline__ void cp_async4(uint32_t s, const void* g) {
    asm volatile("cp.async.ca.shared.global [%0], [%1], 4;" :: "r"(s), "l"(g));
}
__device__ __forceinline__ void cp_async16(uint32_t s, const void* g) {
    asm volatile("cp.async.cg.shared.global [%0], [%1], 16;" :: "r"(s), "l"(g));
}
#define CP_COMMIT() asm volatile("cp.async.commit_group;" ::: "memory")
#define CP_WAIT0()  asm volatile("cp.async.wait_group 0;" ::: "memory")

// ---------------- tiled transpose: out[b,c,w,h] = in[b,c,h,w] ----------------
__global__ void transpose_kernel(const float* __restrict__ in, float* __restrict__ out)
{
    __shared__ float ts[32][33];
    const int tile = blockIdx.x;            // 0..8
    const int plane = blockIdx.y;           // b*C + c
    const int h0 = (tile % 3) * 32, w0 = (tile / 3) * 32;
    const float* ib = in + (size_t)plane * PIX;
    float* ob = out + (size_t)plane * PIX;
    const int col = threadIdx.x & 31, row = threadIdx.x >> 5;
    #pragma unroll
    for (int r = 0; r < 4; r++) {
        int h = row + r*8;
        ts[h][col] = ib[(h0 + h)*HW + w0 + col];
    }
    __syncthreads();
    #pragma unroll
    for (int r = 0; r < 4; r++) {
        int w = row + r*8;
        ob[(w0 + w)*HW + h0 + col] = ts[col][w];
    }
}

// ---------------- prep: pack x / xT into half2 channel pairs -----------------
__global__ void pack_x2_kernel(const float* __restrict__ x, const float* __restrict__ xT,
                               uint32_t* __restrict__ x2, uint32_t* __restrict__ x2T)
{
    size_t idx = (size_t)blockIdx.x * 256 + threadIdx.x;      // < NB*128*PIX
    const float* src = blockIdx.y ? xT : x;
    uint32_t* dst    = blockIdx.y ? x2T : x2;
    size_t bp = idx / PIX, pix = idx % PIX;
    size_t b = bp >> 7, pr = bp & 127;
    const float* s = src + (b*NC + 2*pr) * (size_t)PIX + pix;
    dst[idx] = pack_h2(s[0], s[PIX]);
}

// ---------------- prep: pack v weights (half2 chunk layout, 16 chunks) -------
__global__ void pack_wv2_kernel(const float* __restrict__ wv_w, const float* __restrict__ wv_h,
                                uint32_t* __restrict__ dst)
{
    int i = blockIdx.x * 256 + threadIdx.x;                   // < 2*NC*1408
    int conv = i / (NC*1408);
    int r = i % (NC*1408);
    int o = r / 1408, k = r % 1408;
    int kc = k / 88, rr = k % 88, c2 = rr / 11, t = rr % 11;
    const float* w = conv ? wv_h : wv_w;
    int c = kc*16 + 2*c2;
    dst[i] = pack_h2(w[(size_t)o*KTOT + c*KK + t], w[(size_t)o*KTOT + (c+1)*KK + t]);
}

// ---------------- prep: pack qk weights (fp32x2 (o,o+16), 32 chunks) ---------
__global__ void pack_wqk2_kernel(const float* __restrict__ w0, const float* __restrict__ w1,
                                 const float* __restrict__ w2, const float* __restrict__ w3,
                                 ull* __restrict__ dst)
{
    int i = blockIdx.x * 256 + threadIdx.x;                   // < 4*16*2816
    int conv = i / (16*2816);
    int r = i % (16*2816);
    int o = r / 2816, k = r % 2816;
    int kc = k / 88, rr = k % 88, c = rr / 11, t = rr % 11;
    const float* w = (conv == 0) ? w0 : (conv == 1) ? w1 : (conv == 2) ? w2 : w3;
    int ch = kc*8 + c;
    dst[i] = pack2(w[(size_t)o*KTOT + ch*KK + t], w[(size_t)(o+16)*KTOT + ch*KK + t]);
}

// ---------------- fp32x2 packed 1-D conv (all 4 q/k convs, cp.async piped) ---
// grid = (96, 4, 16); blockIdx.y selects conv. 32 K-chunks of 8 channels.
__global__ void __launch_bounds__(256) conv1d_qk_kernel(
    const float* __restrict__ x, const float* __restrict__ xT,
    const ull* __restrict__ wpk,
    const float* __restrict__ bq_w, float* __restrict__ qw_o,
    const float* __restrict__ bk_w, float* __restrict__ kw_o,
    const float* __restrict__ bq_h, float* __restrict__ qh_o,
    const float* __restrict__ bk_h, float* __restrict__ kh_o)
{
    constexpr int RQ = 6;
    __shared__ float in_s[2][8][112];        // pos 5..100 valid, halo zero
    __shared__ ull   w2_s[2][16][88];

    const int conv = blockIdx.y;
    const float* in; const float* bias; float* out;
    switch (conv) {
        case 0:  in = x;  bias = bq_w; out = qw_o; break;
        case 1:  in = x;  bias = bk_w; out = kw_o; break;
        case 2:  in = xT; bias = bq_h; out = qh_o; break;
        default: in = xT; bias = bk_h; out = kh_o; break;
    }

    const int tid = threadIdx.x;
    const int tq = tid % 16, to = tid / 16;
    const int p = blockIdx.x, b = blockIdx.z;
    const float* inb = in + (size_t)b * NC * PIX + p * HW;
    const ull* wb = wpk + (size_t)conv * 16 * 2816;

    const uint32_t su_in = (uint32_t)__cvta_generic_to_shared(&in_s[0][0][0]);
    const uint32_t su_w  = (uint32_t)__cvta_generic_to_shared(&w2_s[0][0][0]);

    // zero in_s (covers halos); must complete before first cp.async lands
    for (int i = tid; i < 2*8*112; i += 256)
        (&in_s[0][0][0])[i] = 0.f;
    __syncthreads();

    auto issue_chunk = [&](int kc, int buf) {
        // inputs: 8 rows x 96 words, 4B ops into pos+5
        #pragma unroll
        for (int it = 0; it < 3; it++) {
            int i = tid + it*256;                          // < 768
            int c = i / 96, pos = i % 96;
            uint32_t dst = su_in + (((buf*8 + c)*112) + 5 + pos) * 4;
            cp_async4(dst, inb + (size_t)(kc*8 + c) * PIX + pos);
        }
        // weights: 16 rows x 88 ull = 704 x 16B ops
        #pragma unroll
        for (int it = 0; it < 3; it++) {
            int i = tid + it*256;
            if (i < 704) {
                int o = i / 44, j = i % 44;
                uint32_t dst = su_w + (((buf*16 + o)*88) + j*2) * 8;
                cp_async16(dst, wb + (size_t)o*2816 + kc*88 + j*2);
            }
        }
        CP_COMMIT();
    };

    ull acc[RQ];
    #pragma unroll
    for (int j = 0; j < RQ; j++) acc[j] = 0ull;

    issue_chunk(0, 0);
    int buf = 0;
    for (int kc = 0; kc < 32; kc++) {
        CP_WAIT0();
        __syncthreads();
        if (kc + 1 < 32) issue_chunk(kc + 1, buf ^ 1);
        #pragma unroll 2
        for (int c = 0; c < 8; c++) {
            float xv[16];
            #pragma unroll
            for (int j = 0; j < 16; j++) xv[j] = in_s[buf][c][tq*RQ + j];
            ull xp[16];
            #pragma unroll
            for (int j = 0; j < 16; j++) xp[j] = pack2(xv[j], xv[j]);
            #pragma unroll
            for (int t = 0; t < KK; t++) {
                ull wv = w2_s[buf][to][c*KK + t];
                #pragma unroll
                for (int j = 0; j < RQ; j++)
                    acc[j] = ffma2(wv, xp[j + t], acc[j]);
            }
        }
        buf ^= 1;
    }
    const int oA = to, oB = to + 16;
    const float bA = bias[oA], bB = bias[oB];
    float* obA = out + (size_t)(b * NC8 + oA) * PIX + p * HW + tq*RQ;
    float* obB = out + (size_t)(b * NC8 + oB) * PIX + p * HW + tq*RQ;
    #pragma unroll
    for (int j = 0; j < RQ; j++) {
        float lo, hi;
        unpack2(acc[j], lo, hi);
        obA[j] = lo + bA;
        obB[j] = hi + bB;
    }
}

// ---------------- fp16 MMA 1-D conv (both v convs, cp.async piped) -----------
// Block: 64 oc x 4 lines; 8 warps = wm(0..1: 32-oc half, two m16 tiles) x
// wl(0..3: line). B fragments shared by both tiles -> 1.33 LDS/mma.
// grid = (24, 4, 32); blockIdx.z: low 4 bits = batch, bit 4 = conv.
// 16 K-chunks of 16 channels (8 half2 pairs).
#define V_SMEM ((2*4*8*120 + 2*64*92) * 4)   /* 77824 B */
__global__ void __launch_bounds__(256) conv1d_v_kernel(
    const uint32_t* __restrict__ x2, const uint32_t* __restrict__ x2T,
    const uint32_t* __restrict__ wpk,
    const float* __restrict__ bv_w, float* __restrict__ vw_o,
    const float* __restrict__ bv_h, float* __restrict__ vh_o)
{
    extern __shared__ uint32_t dsm[];
    uint32_t (*in_s)[4][8][120] = reinterpret_cast<uint32_t(*)[4][8][120]>(dsm);
    uint32_t (*w_s)[64][92]     = reinterpret_cast<uint32_t(*)[64][92]>(dsm + 2*4*8*120);

    const int zb = blockIdx.z;
    const int b = zb & 15;
    const int conv = zb >> 4;
    const uint32_t* xp = conv ? x2T : x2;
    const float* bias = conv ? bv_h : bv_w;
    float* out = conv ? vh_o : vw_o;

    const int tid = threadIdx.x;
    const int warp = tid >> 5, lane = tid & 31;
    const int wm = warp & 1;                  // 32-oc half
    const int wl = warp >> 1;                 // line 0..3
    const int krow = lane & 3;
    const int grp  = lane >> 2;
    const int p0 = blockIdx.x * 4;
    const int o0 = blockIdx.y * 64;

    const uint32_t su_in = (uint32_t)__cvta_generic_to_shared(&in_s[0][0][0][0]);
    const uint32_t su_w  = (uint32_t)__cvta_generic_to_shared(&w_s[0][0][0]);
    const uint32_t* xb = xp + ((size_t)b*128) * PIX + p0 * HW;
    const uint32_t* wb = wpk + ((size_t)conv*NC + o0) * 1408;

    // zero in_s (covers halos)
    for (int i = tid; i < 2*4*8*120; i += 256) dsm[i] = 0u;
    __syncthreads();

    auto issue_chunk = [&](int kc, int buf) {
        // inputs: 32 rows (4 lines x 8 c2) x 96 words, 4B ops into pos+5
        #pragma unroll
        for (int it = 0; it < 12; it++) {
            int i = tid + it*256;                          // < 3072
            int row = i / 96, pos = i % 96;
            int l = row >> 3, c2 = row & 7;
            uint32_t dst = su_in + ((((buf*4 + l)*8 + c2)*120) + 5 + pos) * 4;
            cp_async4(dst, xb + (size_t)(kc*8 + c2) * PIX + l*HW + pos);
        }
        // weights: 64 rows x 88 words = 1408 x 16B ops
        #pragma unroll
        for (int it = 0; it < 6; it++) {
            int i = tid + it*256;
            if (i < 1408) {
                int o = i / 22, j = i % 22;
                uint32_t dst = su_w + (((buf*64 + o)*92) + j*4) * 4;
                cp_async16(dst, wb + (size_t)o*1408 + kc*88 + j*4);
            }
        }
        CP_COMMIT();
    };

    float acc[2][12][4];
    #pragma unroll
    for (int m = 0; m < 2; m++)
        #pragma unroll
        for (int nt = 0; nt < 12; nt++)
            #pragma unroll
            for (int r = 0; r < 4; r++) acc[m][nt][r] = 0.f;

    issue_chunk(0, 0);
    int buf = 0;
    for (int kc = 0; kc < 16; kc++) {
        CP_WAIT0();
        __syncthreads();
        if (kc + 1 < 16) issue_chunk(kc + 1, buf ^ 1);
        #pragma unroll
        for (int t = 0; t < KK; t++) {
            const int r0 = wm*32 + grp;
            uint32_t a0 = w_s[buf][r0     ][ krow     *KK + t];
            uint32_t a1 = w_s[buf][r0 +  8][ krow     *KK + t];
            uint32_t a2 = w_s[buf][r0     ][(krow + 4)*KK + t];
            uint32_t a3 = w_s[buf][r0 +  8][(krow + 4)*KK + t];
            uint32_t a4 = w_s[buf][r0 + 16][ krow     *KK + t];
            uint32_t a5 = w_s[buf][r0 + 24][ krow     *KK + t];
            uint32_t a6 = w_s[buf][r0 + 16][(krow + 4)*KK + t];
            uint32_t a7 = w_s[buf][r0 + 24][(krow + 4)*KK + t];
            #pragma unroll
            for (int nt = 0; nt < 12; nt++) {
                int pos = nt*8 + grp + t;
                uint32_t b0 = in_s[buf][wl][krow    ][pos];
                uint32_t b1 = in_s[buf][wl][krow + 4][pos];
                mma_f16(acc[0][nt], a0, a1, a2, a3, b0, b1);
                mma_f16(acc[1][nt], a4, a5, a6, a7, b0, b1);
            }
        }
        buf ^= 1;
    }

    #pragma unroll
    for (int m = 0; m < 2; m++) {
        const int oLo = o0 + wm*32 + m*16 + grp;
        const int oHi = oLo + 8;
        const float bLo = bias[oLo];
        const float bHi = bias[oHi];
        float* obLo = out + (size_t)(b * NC + oLo) * PIX + (p0 + wl) * HW;
        float* obHi = out + (size_t)(b * NC + oHi) * PIX + (p0 + wl) * HW;
        #pragma unroll
        for (int nt = 0; nt < 12; nt++) {
            int q = nt*8 + 2*krow;
            obLo[q]     = acc[m][nt][0] + bLo;
            obLo[q + 1] = acc[m][nt][1] + bLo;
            obHi[q]     = acc[m][nt][2] + bHi;
            obHi[q + 1] = acc[m][nt][3] + bHi;
        }
    }
}

// ---------------- energy (both, merged): E[i,j] = sum_c Q[c,i]*K[c,j] --------
// grid = (96, 16, 2); z=0: (qhT,khT)->eh with diag mask, z=1: (qw,kw)->ew
__global__ void __launch_bounds__(256) energy_kernel(
    const float* __restrict__ qh, const float* __restrict__ kh, float* __restrict__ eh_,
    const float* __restrict__ qw, const float* __restrict__ kw, float* __restrict__ ew_)
{
    __shared__ float q_s[NC8][97], k_s[NC8][97];
    const bool diag = (blockIdx.z == 0);
    const float* q = diag ? qh : qw;
    const float* k = diag ? kh : kw;
    float* e = diag ? eh_ : ew_;
    const int l = blockIdx.x, b = blockIdx.y, tid = threadIdx.x;
    const float* qb = q + (size_t)b * NC8 * PIX + l * HW;
    const float* kb = k + (size_t)b * NC8 * PIX + l * HW;
    for (int idx = tid; idx < NC8*HW; idx += 256) {
        int c = idx / HW, i = idx % HW;
        q_s[c][i] = qb[(size_t)c * PIX + i];
        k_s[c][i] = kb[(size_t)c * PIX + i];
    }
    __syncthreads();
    const int tj = tid % 16, ti = tid / 16;
    float acc[6][6];
    #pragma unroll
    for (int i = 0; i < 6; i++)
        #pragma unroll
        for (int j = 0; j < 6; j++) acc[i][j] = 0.f;
    for (int c = 0; c < NC8; c++) {
        float qa[6], ka[6];
        #pragma unroll
        for (int ii = 0; ii < 6; ii++) qa[ii] = q_s[c][ii*16 + ti];
        #pragma unroll
        for (int jj = 0; jj < 6; jj++) ka[jj] = k_s[c][jj*16 + tj];
        #pragma unroll
        for (int ii = 0; ii < 6; ii++)
            #pragma unroll
            for (int jj = 0; jj < 6; jj++)
                acc[ii][jj] = fmaf(qa[ii], ka[jj], acc[ii][jj]);
    }
    float* eb = e + (size_t)(b * HW + l) * PIX;
    #pragma unroll
    for (int ii = 0; ii < 6; ii++)
        #pragma unroll
        for (int jj = 0; jj < 6; jj++) {
            int i = ii*16 + ti, j = jj*16 + tj;
            eb[i*HW + j] = (diag && i == j) ? -INFINITY : acc[ii][jj];
        }
}

// ---------------- softmax over concat[e_h(96), e_w(96)], in place ------------
__global__ void softmax_kernel(float* __restrict__ eh, float* __restrict__ ew)
{
    const int gw = (blockIdx.x * blockDim.x + threadIdx.x) >> 5;   // pixel id
    const int lane = threadIdx.x & 31;
    const int b = gw / PIX, rem = gw % PIX, h = rem / HW, w = rem % HW;
    float* ph = eh + ((size_t)(b*HW + w) * HW + h) * HW;
    float* pw = ew + ((size_t)(b*HW + h) * HW + w) * HW;
    float v[6];
    v[0] = ph[lane]; v[1] = ph[lane+32]; v[2] = ph[lane+64];
    v[3] = pw[lane]; v[4] = pw[lane+32]; v[5] = pw[lane+64];
    float m = v[0];
    #pragma unroll
    for (int r = 1; r < 6; r++) m = fmaxf(m, v[r]);
    #pragma unroll
    for (int s = 16; s; s >>= 1) m = fmaxf(m, __shfl_xor_sync(0xffffffffu, m, s));
    float sum = 0.f;
    #pragma unroll
    for (int r = 0; r < 6; r++) { v[r] = expf(v[r] - m); sum += v[r]; }
    #pragma unroll
    for (int s = 16; s; s >>= 1) sum += __shfl_xor_sync(0xffffffffu, sum, s);
    float inv = 1.f / sum;
    ph[lane]    = v[0]*inv; ph[lane+32] = v[1]*inv; ph[lane+64] = v[2]*inv;
    pw[lane]    = v[3]*inv; pw[lane+32] = v[4]*inv; pw[lane+64] = v[5]*inv;
}

// ---------------- apply (both, merged, scalar R13 body) ----------------------
// grid = (96, 16, 2); z=0: (vw, ew)->tmp, z=1: (vhT, eh)->ohT.
#define OUT_SMEM ((96*97 + 64*97) * 4)   /* 62080 B */
__global__ void __launch_bounds__(256) out_kernel(
    const float* __restrict__ vw, const float* __restrict__ aw, float* __restrict__ ow,
    const float* __restrict__ vh, const float* __restrict__ ah, float* __restrict__ oh)
{
    extern __shared__ float sh[];
    float (*A_s)[97] = reinterpret_cast<float(*)[97]>(sh);           // [96][97] A^T
    float (*V_s)[97] = reinterpret_cast<float(*)[97]>(sh + 96*97);   // [64][97]
    const float* v; const float* a; float* o;
    if (blockIdx.z == 0) { v = vw; a = aw; o = ow; }
    else                 { v = vh; a = ah; o = oh; }
    const int l = blockIdx.x, b = blockIdx.y, tid = threadIdx.x;
    const float* ab = a + (size_t)(b*HW + l) * PIX;
    for (int idx = tid; idx < PIX; idx += 256) {
        int qq = idx / HW, kk = idx % HW;
        A_s[kk][qq] = ab[idx];
    }
    const float* vb = v + (size_t)b * NC * PIX + l * HW;
    float* ob = o + (size_t)b * NC * PIX + l * HW;
    const int tq = tid % 16, tc = tid / 16;
    for (int c0 = 0; c0 < NC; c0 += 64) {
        __syncthreads();
        for (int idx = tid; idx < 64*HW; idx += 256) {
            int cc = idx / HW, kk = idx % HW;
            V_s[cc][kk] = vb[(size_t)(c0 + cc) * PIX + kk];
        }
        __syncthreads();
        float acc[4][6];
        #pragma unroll
        for (int i = 0; i < 4; i++)
            #pragma unroll
            for (int j = 0; j < 6; j++) acc[i][j] = 0.f;
        #pragma unroll 4
        for (int kk = 0; kk < HW; kk++) {
            float va[4], aa[6];
            #pragma unroll
            for (int i = 0; i < 4; i++) va[i] = V_s[tc*4 + i][kk];
            #pragma unroll
            for (int j = 0; j < 6; j++) aa[j] = A_s[kk][j*16 + tq];
            #pragma unroll
            for (int i = 0; i < 4; i++)
                #pragma unroll
                for (int j = 0; j < 6; j++)
                    acc[i][j] = fmaf(va[i], aa[j], acc[i][j]);
        }
        #pragma unroll
        for (int i = 0; i < 4; i++)
            #pragma unroll
            for (int j = 0; j < 6; j++)
                ob[(size_t)(c0 + tc*4 + i) * PIX + j*16 + tq] = acc[i][j];
    }
}

// ---------------- final: out = gamma*(ohT^T + tmp) + x -----------------------
__global__ void fuse_kernel(const float* __restrict__ ohT, const float* __restrict__ tmp,
                            const float* __restrict__ x, const float* __restrict__ gamma,
                            float* __restrict__ out)
{
    __shared__ float ts[32][33];
    const int tile = blockIdx.x, plane = blockIdx.y;
    const int h0 = (tile % 3) * 32, w0 = (tile / 3) * 32;
    const size_t base = (size_t)plane * PIX;
    const int col = threadIdx.x & 31, row = threadIdx.x >> 5;
    #pragma unroll
    for (int r = 0; r < 4; r++) {
        int w = row + r*8;
        ts[w][col] = ohT[base + (w0 + w)*HW + h0 + col];
    }
    __syncthreads();
    const float g = *gamma;
    #pragma unroll
    for (int r = 0; r < 4; r++) {
        int h = row + r*8;
        size_t idx = base + (h0 + h)*HW + w0 + col;
        out[idx] = g * (ts[col][h] + tmp[idx]) + x[idx];
    }
}

// ---------------- launch ------------------------------------------------------
extern "C" void kernel_launch(void* const* d_in, const int* in_sizes, int n_in,
                              void* d_out, int out_size)
{
    (void)in_sizes; (void)n_in; (void)out_size;
    const float* x     = (const float*)d_in[0];
    const float* wq_h  = (const float*)d_in[1];
    const float* bq_h  = (const float*)d_in[2];
    const float* wq_w  = (const float*)d_in[3];
    const float* bq_w  = (const float*)d_in[4];
    const float* wk_h  = (const float*)d_in[5];
    const float* bk_h  = (const float*)d_in[6];
    const float* wk_w  = (const float*)d_in[7];
    const float* bk_w  = (const float*)d_in[8];
    const float* wv_h  = (const float*)d_in[9];
    const float* bv_h  = (const float*)d_in[10];
    const float* wv_w  = (const float*)d_in[11];
    const float* bv_w  = (const float*)d_in[12];
    const float* gamma = (const float*)d_in[13];
    float* out = (float*)d_out;

    float *xT, *qw, *kw, *qhT, *khT, *vw, *vhT, *eh, *ew, *tmp;
    uint32_t *x2, *x2T, *wv2; ull* wqk2;
    cudaGetSymbolAddress((void**)&xT,  g_xT);
    cudaGetSymbolAddress((void**)&qw,  g_qw);
    cudaGetSymbolAddress((void**)&kw,  g_kw);
    cudaGetSymbolAddress((void**)&qhT, g_qhT);
    cudaGetSymbolAddress((void**)&khT, g_khT);
    cudaGetSymbolAddress((void**)&vw,  g_vw);
    cudaGetSymbolAddress((void**)&vhT, g_vhT);
    cudaGetSymbolAddress((void**)&eh,  g_eh);
    cudaGetSymbolAddress((void**)&ew,  g_ew);
    cudaGetSymbolAddress((void**)&tmp, g_tmp);
    cudaGetSymbolAddress((void**)&x2,  g_x2);
    cudaGetSymbolAddress((void**)&x2T, g_x2T);
    cudaGetSymbolAddress((void**)&wv2, g_wv2);
    cudaGetSymbolAddress((void**)&wqk2, g_wqk2);
    float* ohT = xT;   // reuse: xT dead after conv phase

    cudaFuncSetAttribute((const void*)out_kernel,
                         cudaFuncAttributeMaxDynamicSharedMemorySize, OUT_SMEM);
    cudaFuncSetAttribute((const void*)conv1d_v_kernel,
                         cudaFuncAttributeMaxDynamicSharedMemorySize, V_SMEM);

    // 1) transpose x; pack operands into smem bit-layouts
    transpose_kernel<<<dim3(9, NB*NC), 256>>>(x, xT);
    pack_x2_kernel<<<dim3(NB*128*PIX/256, 2), 256>>>(x, xT, x2, x2T);
    pack_wv2_kernel<<<2*NC*1408/256, 256>>>(wv_w, wv_h, wv2);
    pack_wqk2_kernel<<<4*16*2816/256, 256>>>(wq_w, wk_w, wq_h, wk_h, wqk2);
    // 2) q/k convs (fp32x2 FFMA2, cp.async double-buffered)
    conv1d_qk_kernel<<<dim3(HW, 4, NB), 256>>>(
        x, xT, wqk2,
        bq_w, qw, bk_w, kw, bq_h, qhT, bk_h, khT);
    //    v convs (fp16 mma, 32 oc/warp, cp.async double-buffered)
    conv1d_v_kernel<<<dim3(HW/4, NC/64, 2*NB), 256, V_SMEM>>>(
        x2, x2T, wv2, bv_w, vw, bv_h, vhT);
    // 3) energies, one launch (+ diag mask on e_h)
    energy_kernel<<<dim3(HW, NB, 2), 256>>>(qhT, khT, eh, qw, kw, ew);
    // 4) joint softmax over 192, in place -> attention maps
    softmax_kernel<<<(NB*PIX)/8, 256>>>(eh, ew);
    // 5) apply attention, one launch (scalar body, 62 KB smem, 3 blocks/SM)
    out_kernel<<<dim3(HW, NB, 2), 256, OUT_SMEM>>>(vw, ew, tmp, vhT, eh, ohT);
    // 6) fuse: gamma*(out_h + out_w) + x
    fuse_kernel<<<dim3(9, NB*NC), 256>>>(ohT, tmp, x, gamma, out);
}

// round 16
// speedup vs baseline: 1.0871x; 1.0313x over previous
#include <cuda_runtime.h>
#include <cuda_fp16.h>
#include <math.h>
#include <stdint.h>

#define NB   16
#define NC   256
#define NC8  32
#define HW   96
#define PIX  (HW*HW)     /* 9216 */
#define KK   11
#define KTOT (NC*KK)     /* 2816 */

typedef unsigned long long ull;

// ---------------- scratch (static device globals; no allocation) -------------
__device__ float g_xT [NB*NC*PIX];    // x transposed [b,c,w,h]; reused as ohT later
__device__ float g_qw [NB*NC8*PIX];
__device__ float g_kw [NB*NC8*PIX];
__device__ float g_qhT[NB*NC8*PIX];
__device__ float g_khT[NB*NC8*PIX];
__device__ float g_vw [NB*NC*PIX];
__device__ float g_vhT[NB*NC*PIX];
__device__ float g_eh [NB*HW*PIX];    // [b,w,h,H]
__device__ float g_ew [NB*HW*PIX];    // [b,h,w,W]
__device__ float g_tmp[NB*NC*PIX];    // out_w in normal layout
// pre-packed operands (smem bit-layouts, enables cp.async staging)
__device__ __align__(16) uint32_t g_x2  [NB*128*PIX];   // half2(x[2p], x[2p+1])
__device__ __align__(16) uint32_t g_x2T [NB*128*PIX];
__device__ __align__(16) uint32_t g_wv2 [2*NC*1408];    // [conv][o][kc*88 + c2*11 + t], 16 chunks
__device__ __align__(16) ull      g_wqk2[4*16*2816];    // [conv][opair][kc*88 + c*11 + t], 32 chunks

// ---------------- helpers ----------------------------------------------------
__device__ __forceinline__ uint32_t pack_h2(float a, float b) {
    __half2 h = __floats2half2_rn(a, b);
    return *reinterpret_cast<uint32_t*>(&h);
}

__device__ __forceinline__ void mma_f16(float c[4],
    uint32_t a0, uint32_t a1, uint32_t a2, uint32_t a3,
    uint32_t b0, uint32_t b1)
{
    asm volatile(
        "mma.sync.aligned.m16n8k16.row.col.f32.f16.f16.f32 "
        "{%0,%1,%2,%3}, {%4,%5,%6,%7}, {%8,%9}, {%0,%1,%2,%3};"
        : "+f"(c[0]), "+f"(c[1]), "+f"(c[2]), "+f"(c[3])
        : "r"(a0), "r"(a1), "r"(a2), "r"(a3), "r"(b0), "r"(b1));
}

// packed fp32x2: two exact IEEE fp32 FMAs per instruction (Blackwell FFMA2)
__device__ __forceinline__ ull ffma2(ull a, ull b, ull c) {
    ull d;
    asm("fma.rn.f32x2 %0, %1, %2, %3;" : "=l"(d) : "l"(a), "l"(b), "l"(c));
    return d;
}
__device__ __forceinline__ ull pack2(float lo, float hi) {
    ull r;
    asm("mov.b64 %0, {%1, %2};" : "=l"(r) : "f"(lo), "f"(hi));
    return r;
}
__device__ __forceinline__ void unpack2(ull v, float& lo, float& hi) {
    asm("mov.b64 {%0, %1}, %2;" : "=f"(lo), "=f"(hi) : "l"(v));
}

__device__ __forceinline__ void cp_async4(uint32_t s, const void* g) {
    asm volatile("cp.async.ca.shared.global [%0], [%1], 4;" :: "r"(s), "l"(g));
}
__device__ __forceinline__ void cp_async16(uint32_t s, const void* g) {
    asm volatile("cp.async.cg.shared.global [%0], [%1], 16;" :: "r"(s), "l"(g));
}
#define CP_COMMIT() asm volatile("cp.async.commit_group;" ::: "memory")
#define CP_WAIT0()  asm volatile("cp.async.wait_group 0;" ::: "memory")

// ---------------- tiled transpose: out[b,c,w,h] = in[b,c,h,w] ----------------
__global__ void transpose_kernel(const float* __restrict__ in, float* __restrict__ out)
{
    __shared__ float ts[32][33];
    const int tile = blockIdx.x;            // 0..8
    const int plane = blockIdx.y;           // b*C + c
    const int h0 = (tile % 3) * 32, w0 = (tile / 3) * 32;
    const float* ib = in + (size_t)plane * PIX;
    float* ob = out + (size_t)plane * PIX;
    const int col = threadIdx.x & 31, row = threadIdx.x >> 5;
    #pragma unroll
    for (int r = 0; r < 4; r++) {
        int h = row + r*8;
        ts[h][col] = ib[(h0 + h)*HW + w0 + col];
    }
    __syncthreads();
    #pragma unroll
    for (int r = 0; r < 4; r++) {
        int w = row + r*8;
        ob[(w0 + w)*HW + h0 + col] = ts[col][w];
    }
}

// ---------------- prep: pack x / xT into half2 channel pairs -----------------
__global__ void pack_x2_kernel(const float* __restrict__ x, const float* __restrict__ xT,
                               uint32_t* __restrict__ x2, uint32_t* __restrict__ x2T)
{
    size_t idx = (size_t)blockIdx.x * 256 + threadIdx.x;      // < NB*128*PIX
    const float* src = blockIdx.y ? xT : x;
    uint32_t* dst    = blockIdx.y ? x2T : x2;
    size_t bp = idx / PIX, pix = idx % PIX;
    size_t b = bp >> 7, pr = bp & 127;
    const float* s = src + (b*NC + 2*pr) * (size_t)PIX + pix;
    dst[idx] = pack_h2(s[0], s[PIX]);
}

// ---------------- prep: pack v weights (half2 chunk layout, 16 chunks) -------
__global__ void pack_wv2_kernel(const float* __restrict__ wv_w, const float* __restrict__ wv_h,
                                uint32_t* __restrict__ dst)
{
    int i = blockIdx.x * 256 + threadIdx.x;                   // < 2*NC*1408
    int conv = i / (NC*1408);
    int r = i % (NC*1408);
    int o = r / 1408, k = r % 1408;
    int kc = k / 88, rr = k % 88, c2 = rr / 11, t = rr % 11;
    const float* w = conv ? wv_h : wv_w;
    int c = kc*16 + 2*c2;
    dst[i] = pack_h2(w[(size_t)o*KTOT + c*KK + t], w[(size_t)o*KTOT + (c+1)*KK + t]);
}

// ---------------- prep: pack qk weights (fp32x2 (o,o+16), 32 chunks) ---------
__global__ void pack_wqk2_kernel(const float* __restrict__ w0, const float* __restrict__ w1,
                                 const float* __restrict__ w2, const float* __restrict__ w3,
                                 ull* __restrict__ dst)
{
    int i = blockIdx.x * 256 + threadIdx.x;                   // < 4*16*2816
    int conv = i / (16*2816);
    int r = i % (16*2816);
    int o = r / 2816, k = r % 2816;
    int kc = k / 88, rr = k % 88, c = rr / 11, t = rr % 11;
    const float* w = (conv == 0) ? w0 : (conv == 1) ? w1 : (conv == 2) ? w2 : w3;
    int ch = kc*8 + c;
    dst[i] = pack2(w[(size_t)o*KTOT + ch*KK + t], w[(size_t)(o+16)*KTOT + ch*KK + t]);
}

// ---------------- fp32x2 packed 1-D conv (all 4 q/k convs, cp.async piped) ---
// grid = (96, 4, 16); blockIdx.y selects conv. 32 K-chunks of 8 channels.
__global__ void __launch_bounds__(256) conv1d_qk_kernel(
    const float* __restrict__ x, const float* __restrict__ xT,
    const ull* __restrict__ wpk,
    const float* __restrict__ bq_w, float* __restrict__ qw_o,
    const float* __restrict__ bk_w, float* __restrict__ kw_o,
    const float* __restrict__ bq_h, float* __restrict__ qh_o,
    const float* __restrict__ bk_h, float* __restrict__ kh_o)
{
    constexpr int RQ = 6;
    __shared__ float in_s[2][8][112];        // pos 5..100 valid, halo zero
    __shared__ ull   w2_s[2][16][88];

    const int conv = blockIdx.y;
    const float* in; const float* bias; float* out;
    switch (conv) {
        case 0:  in = x;  bias = bq_w; out = qw_o; break;
        case 1:  in = x;  bias = bk_w; out = kw_o; break;
        case 2:  in = xT; bias = bq_h; out = qh_o; break;
        default: in = xT; bias = bk_h; out = kh_o; break;
    }

    const int tid = threadIdx.x;
    const int tq = tid % 16, to = tid / 16;
    const int p = blockIdx.x, b = blockIdx.z;
    const float* inb = in + (size_t)b * NC * PIX + p * HW;
    const ull* wb = wpk + (size_t)conv * 16 * 2816;

    const uint32_t su_in = (uint32_t)__cvta_generic_to_shared(&in_s[0][0][0]);
    const uint32_t su_w  = (uint32_t)__cvta_generic_to_shared(&w2_s[0][0][0]);

    // zero in_s (covers halos); must complete before first cp.async lands
    for (int i = tid; i < 2*8*112; i += 256)
        (&in_s[0][0][0])[i] = 0.f;
    __syncthreads();

    auto issue_chunk = [&](int kc, int buf) {
        // inputs: 8 rows x 96 words, 4B ops into pos+5
        #pragma unroll
        for (int it = 0; it < 3; it++) {
            int i = tid + it*256;                          // < 768
            int c = i / 96, pos = i % 96;
            uint32_t dst = su_in + (((buf*8 + c)*112) + 5 + pos) * 4;
            cp_async4(dst, inb + (size_t)(kc*8 + c) * PIX + pos);
        }
        // weights: 16 rows x 88 ull = 704 x 16B ops
        #pragma unroll
        for (int it = 0; it < 3; it++) {
            int i = tid + it*256;
            if (i < 704) {
                int o = i / 44, j = i % 44;
                uint32_t dst = su_w + (((buf*16 + o)*88) + j*2) * 8;
                cp_async16(dst, wb + (size_t)o*2816 + kc*88 + j*2);
            }
        }
        CP_COMMIT();
    };

    ull acc[RQ];
    #pragma unroll
    for (int j = 0; j < RQ; j++) acc[j] = 0ull;

    issue_chunk(0, 0);
    int buf = 0;
    for (int kc = 0; kc < 32; kc++) {
        CP_WAIT0();
        __syncthreads();
        if (kc + 1 < 32) issue_chunk(kc + 1, buf ^ 1);
        #pragma unroll 2
        for (int c = 0; c < 8; c++) {
            float xv[16];
            #pragma unroll
            for (int j = 0; j < 16; j++) xv[j] = in_s[buf][c][tq*RQ + j];
            ull xp[16];
            #pragma unroll
            for (int j = 0; j < 16; j++) xp[j] = pack2(xv[j], xv[j]);
            #pragma unroll
            for (int t = 0; t < KK; t++) {
                ull wv = w2_s[buf][to][c*KK + t];
                #pragma unroll
                for (int j = 0; j < RQ; j++)
                    acc[j] = ffma2(wv, xp[j + t], acc[j]);
            }
        }
        buf ^= 1;
    }
    const int oA = to, oB = to + 16;
    const float bA = bias[oA], bB = bias[oB];
    float* obA = out + (size_t)(b * NC8 + oA) * PIX + p * HW + tq*RQ;
    float* obB = out + (size_t)(b * NC8 + oB) * PIX + p * HW + tq*RQ;
    #pragma unroll
    for (int j = 0; j < RQ; j++) {
        float lo, hi;
        unpack2(acc[j], lo, hi);
        obA[j] = lo + bA;
        obB[j] = hi + bB;
    }
}

// ---------------- fp16 MMA 1-D conv (both v convs, cp.async piped) -----------
// Block: 64 oc x 4 lines; 8 warps = wm(0..1: 32-oc half, two m16 tiles) x
// wl(0..3: line). B fragments shared by both tiles -> 1.33 LDS/mma.
// grid = (24, 4, 32); blockIdx.z: low 4 bits = batch, bit 4 = conv.
// 16 K-chunks of 16 channels (8 half2 pairs).
#define V_SMEM ((2*4*8*120 + 2*64*92) * 4)   /* 77824 B */
__global__ void __launch_bounds__(256) conv1d_v_kernel(
    const uint32_t* __restrict__ x2, const uint32_t* __restrict__ x2T,
    const uint32_t* __restrict__ wpk,
    const float* __restrict__ bv_w, float* __restrict__ vw_o,
    const float* __restrict__ bv_h, float* __restrict__ vh_o)
{
    extern __shared__ uint32_t dsm[];
    uint32_t (*in_s)[4][8][120] = reinterpret_cast<uint32_t(*)[4][8][120]>(dsm);
    uint32_t (*w_s)[64][92]     = reinterpret_cast<uint32_t(*)[64][92]>(dsm + 2*4*8*120);

    const int zb = blockIdx.z;
    const int b = zb & 15;
    const int conv = zb >> 4;
    const uint32_t* xp = conv ? x2T : x2;
    const float* bias = conv ? bv_h : bv_w;
    float* out = conv ? vh_o : vw_o;

    const int tid = threadIdx.x;
    const int warp = tid >> 5, lane = tid & 31;
    const int wm = warp & 1;                  // 32-oc half
    const int wl = warp >> 1;                 // line 0..3
    const int krow = lane & 3;
    const int grp  = lane >> 2;
    const int p0 = blockIdx.x * 4;
    const int o0 = blockIdx.y * 64;

    const uint32_t su_in = (uint32_t)__cvta_generic_to_shared(&in_s[0][0][0][0]);
    const uint32_t su_w  = (uint32_t)__cvta_generic_to_shared(&w_s[0][0][0]);
    const uint32_t* xb = xp + ((size_t)b*128) * PIX + p0 * HW;
    const uint32_t* wb = wpk + ((size_t)conv*NC + o0) * 1408;

    // zero in_s (covers halos)
    for (int i = tid; i < 2*4*8*120; i += 256) dsm[i] = 0u;
    __syncthreads();

    auto issue_chunk = [&](int kc, int buf) {
        // inputs: 32 rows (4 lines x 8 c2) x 96 words, 4B ops into pos+5
        #pragma unroll
        for (int it = 0; it < 12; it++) {
            int i = tid + it*256;                          // < 3072
            int row = i / 96, pos = i % 96;
            int l = row >> 3, c2 = row & 7;
            uint32_t dst = su_in + ((((buf*4 + l)*8 + c2)*120) + 5 + pos) * 4;
            cp_async4(dst, xb + (size_t)(kc*8 + c2) * PIX + l*HW + pos);
        }
        // weights: 64 rows x 88 words = 1408 x 16B ops
        #pragma unroll
        for (int it = 0; it < 6; it++) {
            int i = tid + it*256;
            if (i < 1408) {
                int o = i / 22, j = i % 22;
                uint32_t dst = su_w + (((buf*64 + o)*92) + j*4) * 4;
                cp_async16(dst, wb + (size_t)o*1408 + kc*88 + j*4);
            }
        }
        CP_COMMIT();
    };

    float acc[2][12][4];
    #pragma unroll
    for (int m = 0; m < 2; m++)
        #pragma unroll
        for (int nt = 0; nt < 12; nt++)
            #pragma unroll
            for (int r = 0; r < 4; r++) acc[m][nt][r] = 0.f;

    issue_chunk(0, 0);
    int buf = 0;
    for (int kc = 0; kc < 16; kc++) {
        CP_WAIT0();
        __syncthreads();
        if (kc + 1 < 16) issue_chunk(kc + 1, buf ^ 1);
        #pragma unroll
        for (int t = 0; t < KK; t++) {
            const int r0 = wm*32 + grp;
            uint32_t a0 = w_s[buf][r0     ][ krow     *KK + t];
            uint32_t a1 = w_s[buf][r0 +  8][ krow     *KK + t];
            uint32_t a2 = w_s[buf][r0     ][(krow + 4)*KK + t];
            uint32_t a3 = w_s[buf][r0 +  8][(krow + 4)*KK + t];
            uint32_t a4 = w_s[buf][r0 + 16][ krow     *KK + t];
            uint32_t a5 = w_s[buf][r0 + 24][ krow     *KK + t];
            uint32_t a6 = w_s[buf][r0 + 16][(krow + 4)*KK + t];
            uint32_t a7 = w_s[buf][r0 + 24][(krow + 4)*KK + t];
            #pragma unroll
            for (int nt = 0; nt < 12; nt++) {
                int pos = nt*8 + grp + t;
                uint32_t b0 = in_s[buf][wl][krow    ][pos];
                uint32_t b1 = in_s[buf][wl][krow + 4][pos];
                mma_f16(acc[0][nt], a0, a1, a2, a3, b0, b1);
                mma_f16(acc[1][nt], a4, a5, a6, a7, b0, b1);
            }
        }
        buf ^= 1;
    }

    #pragma unroll
    for (int m = 0; m < 2; m++) {
        const int oLo = o0 + wm*32 + m*16 + grp;
        const int oHi = oLo + 8;
        const float bLo = bias[oLo];
        const float bHi = bias[oHi];
        float* obLo = out + (size_t)(b * NC + oLo) * PIX + (p0 + wl) * HW;
        float* obHi = out + (size_t)(b * NC + oHi) * PIX + (p0 + wl) * HW;
        #pragma unroll
        for (int nt = 0; nt < 12; nt++) {
            int q = nt*8 + 2*krow;
            obLo[q]     = acc[m][nt][0] + bLo;
            obLo[q + 1] = acc[m][nt][1] + bLo;
            obHi[q]     = acc[m][nt][2] + bHi;
            obHi[q + 1] = acc[m][nt][3] + bHi;
        }
    }
}

// ---------------- energy (both, merged): E[i,j] = sum_c Q[c,i]*K[c,j] --------
// grid = (96, 16, 2); z=0: (qhT,khT)->eh with diag mask, z=1: (qw,kw)->ew
__global__ void __launch_bounds__(256) energy_kernel(
    const float* __restrict__ qh, const float* __restrict__ kh, float* __restrict__ eh_,
    const float* __restrict__ qw, const float* __restrict__ kw, float* __restrict__ ew_)
{
    __shared__ float q_s[NC8][97], k_s[NC8][97];
    const bool diag = (blockIdx.z == 0);
    const float* q = diag ? qh : qw;
    const float* k = diag ? kh : kw;
    float* e = diag ? eh_ : ew_;
    const int l = blockIdx.x, b = blockIdx.y, tid = threadIdx.x;
    const float* qb = q + (size_t)b * NC8 * PIX + l * HW;
    const float* kb = k + (size_t)b * NC8 * PIX + l * HW;
    for (int idx = tid; idx < NC8*HW; idx += 256) {
        int c = idx / HW, i = idx % HW;
        q_s[c][i] = qb[(size_t)c * PIX + i];
        k_s[c][i] = kb[(size_t)c * PIX + i];
    }
    __syncthreads();
    const int tj = tid % 16, ti = tid / 16;
    float acc[6][6];
    #pragma unroll
    for (int i = 0; i < 6; i++)
        #pragma unroll
        for (int j = 0; j < 6; j++) acc[i][j] = 0.f;
    for (int c = 0; c < NC8; c++) {
        float qa[6], ka[6];
        #pragma unroll
        for (int ii = 0; ii < 6; ii++) qa[ii] = q_s[c][ii*16 + ti];
        #pragma unroll
        for (int jj = 0; jj < 6; jj++) ka[jj] = k_s[c][jj*16 + tj];
        #pragma unroll
        for (int ii = 0; ii < 6; ii++)
            #pragma unroll
            for (int jj = 0; jj < 6; jj++)
                acc[ii][jj] = fmaf(qa[ii], ka[jj], acc[ii][jj]);
    }
    float* eb = e + (size_t)(b * HW + l) * PIX;
    #pragma unroll
    for (int ii = 0; ii < 6; ii++)
        #pragma unroll
        for (int jj = 0; jj < 6; jj++) {
            int i = ii*16 + ti, j = jj*16 + tj;
            eb[i*HW + j] = (diag && i == j) ? -INFINITY : acc[ii][jj];
        }
}

// ---------------- softmax over concat[e_h(96), e_w(96)], in place ------------
__global__ void softmax_kernel(float* __restrict__ eh, float* __restrict__ ew)
{
    const int gw = (blockIdx.x * blockDim.x + threadIdx.x) >> 5;   // pixel id
    const int lane = threadIdx.x & 31;
    const int b = gw / PIX, rem = gw % PIX, h = rem / HW, w = rem % HW;
    float* ph = eh + ((size_t)(b*HW + w) * HW + h) * HW;
    float* pw = ew + ((size_t)(b*HW + h) * HW + w) * HW;
    float v[6];
    v[0] = ph[lane]; v[1] = ph[lane+32]; v[2] = ph[lane+64];
    v[3] = pw[lane]; v[4] = pw[lane+32]; v[5] = pw[lane+64];
    float m = v[0];
    #pragma unroll
    for (int r = 1; r < 6; r++) m = fmaxf(m, v[r]);
    #pragma unroll
    for (int s = 16; s; s >>= 1) m = fmaxf(m, __shfl_xor_sync(0xffffffffu, m, s));
    float sum = 0.f;
    #pragma unroll
    for (int r = 0; r < 6; r++) { v[r] = expf(v[r] - m); sum += v[r]; }
    #pragma unroll
    for (int s = 16; s; s >>= 1) sum += __shfl_xor_sync(0xffffffffu, sum, s);
    float inv = 1.f / sum;
    ph[lane]    = v[0]*inv; ph[lane+32] = v[1]*inv; ph[lane+64] = v[2]*inv;
    pw[lane]    = v[3]*inv; pw[lane+32] = v[4]*inv; pw[lane+64] = v[5]*inv;
}

// ---------------- apply (both, merged, fp16 mma): O[c,q] = sum_k V[c,k]*A[q,k]
// grid = (96, 4, 32); z: low 4 bits = batch, bit 4 = dir (0: vw/ew->tmp,
// 1: vhT/eh->ohT). Block: 64 channels x 96 q, K = 96 (6 k16 chunks).
// Warp = wm(0..3: m16 tile) x wn(0..1: 48-q half). Vs stride 52, As stride 104
// (both A/B fragment LDS patterns verified conflict-free).
__global__ void __launch_bounds__(256) out_kernel(
    const float* __restrict__ vw, const float* __restrict__ aw, float* __restrict__ ow,
    const float* __restrict__ vh, const float* __restrict__ ah, float* __restrict__ oh)
{
    __shared__ uint32_t Vs[64][52];     // half2(V[c][2k], V[c][2k+1])
    __shared__ uint32_t As[48][104];    // half2(A[q][2k], A[q][2k+1]) at [kw][q]
    const int zb = blockIdx.z;
    const int b = zb & 15;
    const float* v; const float* a; float* o;
    if (zb < 16) { v = vw; a = aw; o = ow; }
    else         { v = vh; a = ah; o = oh; }
    const int l = blockIdx.x, c0 = blockIdx.y * 64, tid = threadIdx.x;

    const float* vb = v + (size_t)(b * NC + c0) * PIX + l * HW;
    const float* ab = a + (size_t)(b * HW + l) * PIX;
    for (int idx = tid; idx < 64*48; idx += 256) {
        int c = idx / 48, kw = idx % 48;
        const float* vp = vb + (size_t)c * PIX + 2*kw;
        Vs[c][kw] = pack_h2(vp[0], vp[1]);
    }
    for (int idx = tid; idx < 96*48; idx += 256) {
        int q = idx / 48, kw = idx % 48;
        const float* ap = ab + q * HW + 2*kw;
        As[kw][q] = pack_h2(ap[0], ap[1]);
    }
    __syncthreads();

    const int warp = tid >> 5, lane = tid & 31;
    const int wm = warp & 3;            // m16 tile (16 channels)
    const int wn = warp >> 2;           // q half (48)
    const int krow = lane & 3;
    const int grp  = lane >> 2;

    float acc[6][4];
    #pragma unroll
    for (int nt = 0; nt < 6; nt++)
        #pragma unroll
        for (int r = 0; r < 4; r++) acc[nt][r] = 0.f;

    #pragma unroll
    for (int kc = 0; kc < 6; kc++) {
        uint32_t a0 = Vs[wm*16 + grp    ][kc*8 + krow];
        uint32_t a1 = Vs[wm*16 + grp + 8][kc*8 + krow];
        uint32_t a2 = Vs[wm*16 + grp    ][kc*8 + krow + 4];
        uint32_t a3 = Vs[wm*16 + grp + 8][kc*8 + krow + 4];
        #pragma unroll
        for (int nt = 0; nt < 6; nt++) {
            int q = wn*48 + nt*8 + grp;
            uint32_t b0 = As[kc*8 + krow    ][q];
            uint32_t b1 = As[kc*8 + krow + 4][q];
            mma_f16(acc[nt], a0, a1, a2, a3, b0, b1);
        }
    }

    float* obLo = o + (size_t)(b * NC + c0 + wm*16 + grp    ) * PIX + l * HW;
    float* obHi = o + (size_t)(b * NC + c0 + wm*16 + grp + 8) * PIX + l * HW;
    #pragma unroll
    for (int nt = 0; nt < 6; nt++) {
        int q = wn*48 + nt*8 + 2*krow;
        obLo[q]     = acc[nt][0];
        obLo[q + 1] = acc[nt][1];
        obHi[q]     = acc[nt][2];
        obHi[q + 1] = acc[nt][3];
    }
}

// ---------------- final: out = gamma*(ohT^T + tmp) + x -----------------------
__global__ void fuse_kernel(const float* __restrict__ ohT, const float* __restrict__ tmp,
                            const float* __restrict__ x, const float* __restrict__ gamma,
                            float* __restrict__ out)
{
    __shared__ float ts[32][33];
    const int tile = blockIdx.x, plane = blockIdx.y;
    const int h0 = (tile % 3) * 32, w0 = (tile / 3) * 32;
    const size_t base = (size_t)plane * PIX;
    const int col = threadIdx.x & 31, row = threadIdx.x >> 5;
    #pragma unroll
    for (int r = 0; r < 4; r++) {
        int w = row + r*8;
        ts[w][col] = ohT[base + (w0 + w)*HW + h0 + col];
    }
    __syncthreads();
    const float g = *gamma;
    #pragma unroll
    for (int r = 0; r < 4; r++) {
        int h = row + r*8;
        size_t idx = base + (h0 + h)*HW + w0 + col;
        out[idx] = g * (ts[col][h] + tmp[idx]) + x[idx];
    }
}

// ---------------- launch ------------------------------------------------------
extern "C" void kernel_launch(void* const* d_in, const int* in_sizes, int n_in,
                              void* d_out, int out_size)
{
    (void)in_sizes; (void)n_in; (void)out_size;
    const float* x     = (const float*)d_in[0];
    const float* wq_h  = (const float*)d_in[1];
    const float* bq_h  = (const float*)d_in[2];
    const float* wq_w  = (const float*)d_in[3];
    const float* bq_w  = (const float*)d_in[4];
    const float* wk_h  = (const float*)d_in[5];
    const float* bk_h  = (const float*)d_in[6];
    const float* wk_w  = (const float*)d_in[7];
    const float* bk_w  = (const float*)d_in[8];
    const float* wv_h  = (const float*)d_in[9];
    const float* bv_h  = (const float*)d_in[10];
    const float* wv_w  = (const float*)d_in[11];
    const float* bv_w  = (const float*)d_in[12];
    const float* gamma = (const float*)d_in[13];
    float* out = (float*)d_out;

    float *xT, *qw, *kw, *qhT, *khT, *vw, *vhT, *eh, *ew, *tmp;
    uint32_t *x2, *x2T, *wv2; ull* wqk2;
    cudaGetSymbolAddress((void**)&xT,  g_xT);
    cudaGetSymbolAddress((void**)&qw,  g_qw);
    cudaGetSymbolAddress((void**)&kw,  g_kw);
    cudaGetSymbolAddress((void**)&qhT, g_qhT);
    cudaGetSymbolAddress((void**)&khT, g_khT);
    cudaGetSymbolAddress((void**)&vw,  g_vw);
    cudaGetSymbolAddress((void**)&vhT, g_vhT);
    cudaGetSymbolAddress((void**)&eh,  g_eh);
    cudaGetSymbolAddress((void**)&ew,  g_ew);
    cudaGetSymbolAddress((void**)&tmp, g_tmp);
    cudaGetSymbolAddress((void**)&x2,  g_x2);
    cudaGetSymbolAddress((void**)&x2T, g_x2T);
    cudaGetSymbolAddress((void**)&wv2, g_wv2);
    cudaGetSymbolAddress((void**)&wqk2, g_wqk2);
    float* ohT = xT;   // reuse: xT dead after conv phase

    cudaFuncSetAttribute((const void*)conv1d_v_kernel,
                         cudaFuncAttributeMaxDynamicSharedMemorySize, V_SMEM);

    // 1) transpose x; pack operands into smem bit-layouts
    transpose_kernel<<<dim3(9, NB*NC), 256>>>(x, xT);
    pack_x2_kernel<<<dim3(NB*128*PIX/256, 2), 256>>>(x, xT, x2, x2T);
    pack_wv2_kernel<<<2*NC*1408/256, 256>>>(wv_w, wv_h, wv2);
    pack_wqk2_kernel<<<4*16*2816/256, 256>>>(wq_w, wk_w, wq_h, wk_h, wqk2);
    // 2) q/k convs (fp32x2 FFMA2, cp.async double-buffered)
    conv1d_qk_kernel<<<dim3(HW, 4, NB), 256>>>(
        x, xT, wqk2,
        bq_w, qw, bk_w, kw, bq_h, qhT, bk_h, khT);
    //    v convs (fp16 mma, 32 oc/warp, cp.async double-buffered)
    conv1d_v_kernel<<<dim3(HW/4, NC/64, 2*NB), 256, V_SMEM>>>(
        x2, x2T, wv2, bv_w, vw, bv_h, vhT);
    // 3) energies, one launch (+ diag mask on e_h)
    energy_kernel<<<dim3(HW, NB, 2), 256>>>(qhT, khT, eh, qw, kw, ew);
    // 4) joint softmax over 192, in place -> attention maps
    softmax_kernel<<<(NB*PIX)/8, 256>>>(eh, ew);
    // 5) apply attention, one launch (fp16 mma GEMM per line)
    out_kernel<<<dim3(HW, NC/64, 2*NB), 256>>>(vw, ew, tmp, vhT, eh, ohT);
    // 6) fuse: gamma*(out_h + out_w) + x
    fuse_kernel<<<dim3(9, NB*NC), 256>>>(ohT, tmp, x, gamma, out);
}